// round 15
// baseline (speedup 1.0000x reference)
#include <cuda_runtime.h>
#include <cuda_fp16.h>
#include <math.h>
#include <stdint.h>

#define D 128
#define N_MAX 16384
#define BM 128
#define BNT 128
#define THREADS 512
#define NCHUNKS 14            // tensor chunks per row-tile
#define TPC 8                 // tiles per chunk (even)
#define NITEMS_T (128 * NCHUNKS)
#define GRID_P 148

// SIMT side: col tiles [112, 128) = cols [14336, 16384)
#define SJT0 112
#define SNT 16
#define NITEMS_S 128

// Scratch (allocation-free rule: __device__ globals)
__device__ __half g_z1h[N_MAX * D];   // fp16, pre-scaled by 2/ln2
__device__ __half g_z2h[N_MAX * D];   // fp16
__device__ float g_denom[N_MAX];
__device__ float g_pos[N_MAX];
__device__ int g_ctr;                 // tensor work counter
__device__ int g_ctr2;                // SIMT work counter

// padded smem row stride: 128 fp16 + 8 pad = 136 elems = 272 bytes
#define SROW 272
#define TILE_BYTES (128 * SROW)          // 34816
// tensor kernel smem
#define OFF_A 0
#define OFF_B0 TILE_BYTES
#define OFF_B1 (2 * TILE_BYTES)
#define OFF_RED (3 * TILE_BYTES)
#define OFF_ITEM (OFF_RED + 128 * 4)
#define SMEM_T (OFF_ITEM + 16)          // ~105 KB
// SIMT kernel smem (padded >114KB so 2 SIMT CTAs can't share an SM)
#define OFF_S_A 0
#define OFF_S_B0 TILE_BYTES
#define OFF_S_B1 (2 * TILE_BYTES)
#define OFF_S_ITEM (3 * TILE_BYTES)
#define SMEM_S 118784                    // 116 KB

__device__ __forceinline__ uint32_t smem_u32(const void* p) {
    uint32_t a;
    asm("{ .reg .u64 t; cvta.to.shared.u64 t, %1; cvt.u32.u64 %0, t; }"
        : "=r"(a) : "l"(p));
    return a;
}

__device__ __forceinline__ float warp_sum(float v) {
    #pragma unroll
    for (int off = 16; off > 0; off >>= 1)
        v += __shfl_xor_sync(0xFFFFFFFFu, v, off);
    return v;
}

// One warp per row: fp32 normalize, exact fp32 pos, fp16 copies;
// zeroes g_denom, counters, out[0].
__global__ void norm_kernel(const float* __restrict__ z1,
                            const float* __restrict__ z2,
                            float* __restrict__ out, int N) {
    int warp = (blockIdx.x * blockDim.x + threadIdx.x) >> 5;
    int lane = threadIdx.x & 31;
    if (blockIdx.x == 0 && threadIdx.x == 0) {
        out[0] = 0.0f; g_ctr = 0; g_ctr2 = 0;
    }
    if (warp >= N) return;

    const float4 a = ((const float4*)(z1 + (size_t)warp * D))[lane];
    const float4 b = ((const float4*)(z2 + (size_t)warp * D))[lane];

    float sa = a.x * a.x + a.y * a.y + a.z * a.z + a.w * a.w;
    float sb = b.x * b.x + b.y * b.y + b.z * b.z + b.w * b.w;
    sa = warp_sum(sa);
    sb = warp_sum(sb);

    float inva = 1.0f / fmaxf(sqrtf(sa), 1e-12f);
    float invb = 1.0f / fmaxf(sqrtf(sb), 1e-12f);

    float4 an = make_float4(a.x * inva, a.y * inva, a.z * inva, a.w * inva);
    float4 bn = make_float4(b.x * invb, b.y * invb, b.z * invb, b.w * invb);

    // bake exponent scale 2/ln2 into A so epilogue is a bare ex2.approx
    const float S = 2.8853900817779268f;
    __half2 a01 = __floats2half2_rn(an.x * S, an.y * S);
    __half2 a23 = __floats2half2_rn(an.z * S, an.w * S);
    __half2 b01 = __floats2half2_rn(bn.x, bn.y);
    __half2 b23 = __floats2half2_rn(bn.z, bn.w);

    uint2 pa, pb;
    pa.x = *(uint32_t*)&a01; pa.y = *(uint32_t*)&a23;
    pb.x = *(uint32_t*)&b01; pb.y = *(uint32_t*)&b23;
    ((uint2*)(g_z1h + (size_t)warp * D))[lane] = pa;
    ((uint2*)(g_z2h + (size_t)warp * D))[lane] = pb;

    float d = an.x * bn.x + an.y * bn.y + an.z * bn.z + an.w * bn.w;
    d = warp_sum(d);
    if (lane == 0) {
        g_pos[warp] = 2.0f * d;
        g_denom[warp] = 0.0f;
    }
}

__device__ __forceinline__ void ldsm_x4(uint32_t (&r)[4], uint32_t addr) {
    asm volatile("ldmatrix.sync.aligned.m8n8.x4.shared.b16 {%0,%1,%2,%3}, [%4];"
                 : "=r"(r[0]), "=r"(r[1]), "=r"(r[2]), "=r"(r[3]) : "r"(addr));
}

__device__ __forceinline__ void hmma_f16acc(uint32_t (&c)[2], const uint32_t (&a)[4],
                                            uint32_t b0, uint32_t b1) {
    asm volatile(
        "mma.sync.aligned.m16n8k16.row.col.f16.f16.f16.f16 "
        "{%0,%1}, {%2,%3,%4,%5}, {%6,%7}, {%0,%1};"
        : "+r"(c[0]), "+r"(c[1])
        : "r"(a[0]), "r"(a[1]), "r"(a[2]), "r"(a[3]), "r"(b0), "r"(b1));
}

__device__ __forceinline__ void cp16(uint32_t dst, const void* src) {
    asm volatile("cp.async.cg.shared.global [%0], [%1], 16;"
                 :: "r"(dst), "l"(src) : "memory");
}

// One tile's k-loop accumulating into `acc`, with the epilogue of the
// PREVIOUS tile (`cprev`) interleaved one fragment-group per kk step.
__device__ __forceinline__ void tile_step(
    uint32_t (&acc)[2][4][2], uint32_t (&cprev)[2][4][2],
    uint32_t a_base, uint32_t b_base, float (&rs)[4]) {
    #pragma unroll
    for (int kk = 0; kk < 8; ++kk) {
        const uint32_t koff = (uint32_t)kk * 32;
        uint32_t a[2][4];
        #pragma unroll
        for (int mf = 0; mf < 2; ++mf)
            ldsm_x4(a[mf], a_base + (uint32_t)(mf * 16) * SROW + koff);
        uint32_t bm[2][4];
        #pragma unroll
        for (int nf2 = 0; nf2 < 2; ++nf2)
            ldsm_x4(bm[nf2], b_base + (uint32_t)(nf2 * 16) * SROW + koff);

        #pragma unroll
        for (int mf = 0; mf < 2; ++mf)
            #pragma unroll
            for (int nf = 0; nf < 4; ++nf)
                hmma_f16acc(acc[mf][nf], a[mf],
                            bm[nf >> 1][nf & 1], bm[nf >> 1][(nf & 1) + 2]);

        {   // deferred epilogue chunk: fragment group = kk of previous tile
            const int mf = kk >> 2, nf = kk & 3;
            float2 f0 = __half22float2(*(__half2*)&cprev[mf][nf][0]);
            float2 f1 = __half22float2(*(__half2*)&cprev[mf][nf][1]);
            float e0, e1, e2, e3;
            asm("ex2.approx.f32 %0, %1;" : "=f"(e0) : "f"(f0.x));
            asm("ex2.approx.f32 %0, %1;" : "=f"(e1) : "f"(f0.y));
            asm("ex2.approx.f32 %0, %1;" : "=f"(e2) : "f"(f1.x));
            asm("ex2.approx.f32 %0, %1;" : "=f"(e3) : "f"(f1.y));
            rs[mf * 2 + 0] += e0 + e1;
            rs[mf * 2 + 1] += e2 + e3;
            cprev[mf][nf][0] = 0u;
            cprev[mf][nf][1] = 0u;
        }
    }
}

// ---------------------------------------------------------------------------
// PERSISTENT tensor GEMM (col tiles 0..111) — R9/R14 machinery unchanged.
// Items = (row-tile, chunk of 8 tiles). Bogus epilogue: 14*128=1792/row.
// ---------------------------------------------------------------------------
__global__ void __launch_bounds__(THREADS, 1)
gemm_hmma16_kernel(int N) {
    extern __shared__ char smem[];
    const uint32_t sb = smem_u32(smem);
    const int tid = threadIdx.x;
    const int wid = tid >> 5;
    const int lane = tid & 31;
    const int warp_m = wid >> 2;
    const int warp_n = wid & 3;
    float* red = (float*)(smem + OFF_RED);
    int* item_sm = (int*)(smem + OFF_ITEM);

    const uint32_t a_base = sb + OFF_A +
        (uint32_t)(warp_m * 32 + (lane & 15)) * SROW + (uint32_t)((lane >> 4) * 16);
    const uint32_t b_lane_off =
        (uint32_t)(warp_n * 32 + (lane & 15)) * SROW + (uint32_t)((lane >> 4) * 16);
    const uint32_t b_base0 = sb + OFF_B0 + b_lane_off;
    const uint32_t b_base1 = sb + OFF_B1 + b_lane_off;

    uint32_t c0[2][4][2], c1[2][4][2];
    #pragma unroll
    for (int mf = 0; mf < 2; ++mf)
        #pragma unroll
        for (int nf = 0; nf < 4; ++nf) {
            c0[mf][nf][0] = 0u; c0[mf][nf][1] = 0u;
            c1[mf][nf][0] = 0u; c1[mf][nf][1] = 0u;
        }

    for (;;) {
        if (tid == 0) item_sm[0] = atomicAdd(&g_ctr, 1);
        __syncthreads();
        const int item = item_sm[0];
        if (item >= NITEMS_T) break;
        const int i0 = (item / NCHUNKS) * BM;
        const int jt0 = (item % NCHUNKS) * TPC;

        {
            const uint4* A4 = (const uint4*)(g_z1h + (size_t)i0 * D);
            #pragma unroll
            for (int t = 0; t < 4; ++t) {
                int idx = tid + t * THREADS;
                int r = idx >> 4, c = idx & 15;
                *(uint4*)(smem + OFF_A + r * SROW + c * 16) = A4[idx];
            }
        }
        {
            const char* B = (const char*)(g_z2h + (size_t)jt0 * BNT * D);
            #pragma unroll
            for (int t = 0; t < 4; ++t) {
                int idx = tid + t * THREADS;
                int r = idx >> 4, c = idx & 15;
                cp16(sb + OFF_B0 + r * SROW + c * 16, B + (size_t)r * 256 + c * 16);
            }
            asm volatile("cp.async.commit_group;" ::: "memory");
        }
        if (tid < 128) red[tid] = 0.f;

        float rs[4] = {0.f, 0.f, 0.f, 0.f};

        for (int t = 0; t < TPC; t += 2) {
            __syncthreads();
            {
                const char* B = (const char*)(g_z2h + (size_t)(jt0 + t + 1) * BNT * D);
                #pragma unroll
                for (int u = 0; u < 4; ++u) {
                    int idx = tid + u * THREADS;
                    int r = idx >> 4, ch = idx & 15;
                    cp16(sb + OFF_B1 + r * SROW + ch * 16, B + (size_t)r * 256 + ch * 16);
                }
                asm volatile("cp.async.commit_group;" ::: "memory");
                asm volatile("cp.async.wait_group 1;" ::: "memory");
            }
            __syncthreads();
            tile_step(c0, c1, a_base, b_base0, rs);

            __syncthreads();
            if (t + 2 < TPC) {
                const char* B = (const char*)(g_z2h + (size_t)(jt0 + t + 2) * BNT * D);
                #pragma unroll
                for (int u = 0; u < 4; ++u) {
                    int idx = tid + u * THREADS;
                    int r = idx >> 4, ch = idx & 15;
                    cp16(sb + OFF_B0 + r * SROW + ch * 16, B + (size_t)r * 256 + ch * 16);
                }
                asm volatile("cp.async.commit_group;" ::: "memory");
                asm volatile("cp.async.wait_group 1;" ::: "memory");
            } else {
                asm volatile("cp.async.wait_group 0;" ::: "memory");
            }
            __syncthreads();
            tile_step(c1, c0, a_base, b_base1, rs);
        }

        // final epilogue: c1 holds tile TPC-1 (zero for reuse)
        #pragma unroll
        for (int mf = 0; mf < 2; ++mf) {
            float lo = 0.f, hi = 0.f;
            #pragma unroll
            for (int nf = 0; nf < 4; ++nf) {
                float2 f0 = __half22float2(*(__half2*)&c1[mf][nf][0]);
                float2 f1 = __half22float2(*(__half2*)&c1[mf][nf][1]);
                float e0, e1, e2, e3;
                asm("ex2.approx.f32 %0, %1;" : "=f"(e0) : "f"(f0.x));
                asm("ex2.approx.f32 %0, %1;" : "=f"(e1) : "f"(f0.y));
                asm("ex2.approx.f32 %0, %1;" : "=f"(e2) : "f"(f1.x));
                asm("ex2.approx.f32 %0, %1;" : "=f"(e3) : "f"(f1.y));
                lo += e0 + e1;
                hi += e2 + e3;
                c1[mf][nf][0] = 0u;
                c1[mf][nf][1] = 0u;
            }
            rs[mf * 2 + 0] += lo;
            rs[mf * 2 + 1] += hi;
        }

        #pragma unroll
        for (int i = 0; i < 4; ++i) {
            rs[i] += __shfl_xor_sync(0xFFFFFFFFu, rs[i], 1);
            rs[i] += __shfl_xor_sync(0xFFFFFFFFu, rs[i], 2);
        }
        __syncthreads();
        if ((lane & 3) == 0) {
            #pragma unroll
            for (int mf = 0; mf < 2; ++mf)
                #pragma unroll
                for (int sub = 0; sub < 2; ++sub) {
                    int row = warp_m * 32 + mf * 16 + sub * 8 + (lane >> 2);
                    atomicAdd(&red[row], rs[mf * 2 + sub]);
                }
        }
        __syncthreads();
        if (tid < 128) atomicAdd(&g_denom[i0 + tid], red[tid]);
    }
}

// ---------------------------------------------------------------------------
// SIMT HFMA2 GEMM (col tiles 112..127) — separate kernel, own register file,
// co-resident with the tensor kernel (1 CTA/SM each). 128 threads, microtile
// 8 rows x 4 cols (half2), conflict-free padded smem, double-buffered B.
// ---------------------------------------------------------------------------
__global__ void __launch_bounds__(128, 1)
gemm_simt_kernel(int N) {
    extern __shared__ char smem[];
    const uint32_t sb = smem_u32(smem);
    const int tid = threadIdx.x;
    const int w = tid >> 5;           // 0..3: rows w*32..+31
    const int lane = tid & 31;
    const int tr = lane >> 3;         // 0..3
    const int tc = lane & 7;          // 0..7
    int* item_sm = (int*)(smem + OFF_S_ITEM);

    for (;;) {
        if (tid == 0) item_sm[0] = atomicAdd(&g_ctr2, 1);
        __syncthreads();
        const int item = item_sm[0];
        if (item >= NITEMS_S) break;
        const int i0 = item * 128;

        // load A tile (128 rows x 128 fp16) into padded smem
        {
            const uint4* A4 = (const uint4*)(g_z1h + (size_t)i0 * D);
            #pragma unroll
            for (int t = 0; t < 16; ++t) {
                int idx = tid + t * 128;
                int r = idx >> 4, c = idx & 15;
                *(uint4*)(smem + OFF_S_A + r * SROW + c * 16) = A4[idx];
            }
        }
        // prologue: B col-tile SJT0 -> buf0
        {
            const char* B = (const char*)(g_z2h + (size_t)SJT0 * BNT * D);
            #pragma unroll
            for (int t = 0; t < 16; ++t) {
                int idx = tid + t * 128;
                int r = idx >> 4, c = idx & 15;
                cp16(sb + OFF_S_B0 + r * SROW + c * 16, B + (size_t)r * 256 + c * 16);
            }
            asm volatile("cp.async.commit_group;" ::: "memory");
        }

        // rows handled by this thread: i0 + w*32 + 4*i + tr  (i<8)
        const char* As = smem + OFF_S_A + (uint32_t)(w * 32 + tr) * SROW;
        float rsim[8];
        #pragma unroll
        for (int i = 0; i < 8; ++i) rsim[i] = 0.f;

        for (int ct = 0; ct < SNT; ++ct) {
            __syncthreads();   // prev compute done (and A stores on ct=0)
            if (ct + 1 < SNT) {
                const char* B = (const char*)(g_z2h + (size_t)(SJT0 + ct + 1) * BNT * D);
                uint32_t dst = sb + ((ct + 1) & 1 ? OFF_S_B1 : OFF_S_B0);
                #pragma unroll
                for (int t = 0; t < 16; ++t) {
                    int idx = tid + t * 128;
                    int r = idx >> 4, c = idx & 15;
                    cp16(dst + r * SROW + c * 16, B + (size_t)r * 256 + c * 16);
                }
                asm volatile("cp.async.commit_group;" ::: "memory");
                asm volatile("cp.async.wait_group 1;" ::: "memory");
            } else {
                asm volatile("cp.async.wait_group 0;" ::: "memory");
            }
            __syncthreads();   // current buf visible
            const char* Bb = smem + (ct & 1 ? OFF_S_B1 : OFF_S_B0);

            #pragma unroll
            for (int pass = 0; pass < 4; ++pass) {
                // cols: pass*32 + tc + 8*j (j<4)
                const char* Bp = Bb + (uint32_t)(pass * 32 + tc) * SROW;
                __half2 acc[8][4];
                #pragma unroll
                for (int i = 0; i < 8; ++i)
                    #pragma unroll
                    for (int j = 0; j < 4; ++j)
                        acc[i][j] = __floats2half2_rn(0.f, 0.f);

                #pragma unroll 2
                for (int q = 0; q < 16; ++q) {
                    float4 av4[8], bv4[4];
                    #pragma unroll
                    for (int i = 0; i < 8; ++i)
                        av4[i] = *(const float4*)(As + (uint32_t)(4 * i) * SROW + q * 16);
                    #pragma unroll
                    for (int j = 0; j < 4; ++j)
                        bv4[j] = *(const float4*)(Bp + (uint32_t)(8 * j) * SROW + q * 16);
                    #pragma unroll
                    for (int s = 0; s < 4; ++s) {
                        #pragma unroll
                        for (int i = 0; i < 8; ++i) {
                            __half2 a2 = ((const __half2*)&av4[i])[s];
                            #pragma unroll
                            for (int j = 0; j < 4; ++j) {
                                __half2 b2 = ((const __half2*)&bv4[j])[s];
                                acc[i][j] = __hfma2(a2, b2, acc[i][j]);
                            }
                        }
                    }
                }

                #pragma unroll
                for (int i = 0; i < 8; ++i) {
                    float s = 0.f;
                    #pragma unroll
                    for (int j = 0; j < 4; ++j) {
                        float2 f = __half22float2(acc[i][j]);
                        float e;
                        asm("ex2.approx.f32 %0, %1;" : "=f"(e) : "f"(f.x + f.y));
                        s += e;
                    }
                    rsim[i] += s;
                }
            }
        }

        // reduce over tc (8 lanes) and flush
        #pragma unroll
        for (int i = 0; i < 8; ++i) {
            rsim[i] += __shfl_xor_sync(0xFFFFFFFFu, rsim[i], 1);
            rsim[i] += __shfl_xor_sync(0xFFFFFFFFu, rsim[i], 2);
            rsim[i] += __shfl_xor_sync(0xFFFFFFFFu, rsim[i], 4);
        }
        if (tc == 0) {
            #pragma unroll
            for (int i = 0; i < 8; ++i)
                atomicAdd(&g_denom[i0 + w * 32 + 4 * i + tr], rsim[i]);
        }
        __syncthreads();   // protect item_sm and smem reuse
    }
}

// 64 blocks x 256 threads; lg2.approx; atomicAdd into out[0].
__global__ void loss_kernel(float* __restrict__ out, int N) {
    __shared__ float smr[256];
    const float BOGUS = 128.0f * (float)NCHUNKS;   // tensor bogus epilogues
    const float LN2 = 0.6931471805599453f;
    int i = blockIdx.x * 256 + threadIdx.x;
    float dv = g_denom[i] - BOGUS + 1e-8f;
    float lg;
    asm("lg2.approx.f32 %0, %1;" : "=f"(lg) : "f"(dv));
    float s = lg * LN2 - g_pos[i];
    smr[threadIdx.x] = s;
    __syncthreads();
    #pragma unroll
    for (int off = 128; off > 0; off >>= 1) {
        if (threadIdx.x < off) smr[threadIdx.x] += smr[threadIdx.x + off];
        __syncthreads();
    }
    if (threadIdx.x == 0) atomicAdd(out, smr[0] / (float)N);
}

extern "C" void kernel_launch(void* const* d_in, const int* in_sizes, int n_in,
                              void* d_out, int out_size) {
    const float* z1 = (const float*)d_in[0];
    const float* z2 = (const float*)d_in[1];
    float* out = (float*)d_out;
    const int N = in_sizes[0] / D;  // 16384

    static cudaStream_t s2 = nullptr;
    static cudaEvent_t evA = nullptr, evB = nullptr;
    if (s2 == nullptr) {
        cudaStreamCreateWithFlags(&s2, cudaStreamNonBlocking);
        cudaEventCreateWithFlags(&evA, cudaEventDisableTiming);
        cudaEventCreateWithFlags(&evB, cudaEventDisableTiming);
        cudaFuncSetAttribute(gemm_hmma16_kernel,
                             cudaFuncAttributeMaxDynamicSharedMemorySize,
                             (int)SMEM_T);
        cudaFuncSetAttribute(gemm_simt_kernel,
                             cudaFuncAttributeMaxDynamicSharedMemorySize,
                             (int)SMEM_S);
    }

    norm_kernel<<<(N + 7) / 8, 256>>>(z1, z2, out, N);
    // fork: SIMT gemm on s2, tensor gemm on default, both after norm
    cudaEventRecord(evA, 0);
    cudaStreamWaitEvent(s2, evA, 0);
    gemm_hmma16_kernel<<<GRID_P, THREADS, SMEM_T>>>(N);
    gemm_simt_kernel<<<GRID_P, 128, SMEM_S, s2>>>(N);
    cudaEventRecord(evB, s2);
    cudaStreamWaitEvent(0, evB, 0);
    loss_kernel<<<N / 256, 256>>>(out, N);
}

// round 16
// speedup vs baseline: 1.6796x; 1.6796x over previous
#include <cuda_runtime.h>
#include <cuda_fp16.h>
#include <math.h>
#include <stdint.h>

#define D 128
#define N_MAX 16384
#define BM 128
#define BNT 128
#define THREADS 512
#define JCHUNKS 8
#define NITEMS 1024          // (N/BM) * JCHUNKS
#define GRID_P 148           // persistent CTAs, 1 per SM

// Scratch (allocation-free rule: __device__ globals)
__device__ __half g_z1h[N_MAX * D];   // fp16, pre-scaled by 2/ln2
__device__ __half g_z2h[N_MAX * D];   // fp16
__device__ float g_denom[N_MAX];
__device__ float g_pos[N_MAX];
__device__ int g_ctr;                 // work counter
__device__ int g_done;                // completion counter

// padded smem row stride: 128 fp16 + 8 pad = 136 elems = 272 bytes
#define SROW 272
#define TILE_BYTES (128 * SROW)          // 34816
#define OFF_A 0
#define OFF_B0 TILE_BYTES
#define OFF_B1 (2 * TILE_BYTES)
#define OFF_RED (3 * TILE_BYTES)
#define OFF_ITEM (OFF_RED + 128 * 4)
#define SMEM_BYTES (OFF_ITEM + 16)

__device__ __forceinline__ uint32_t smem_u32(const void* p) {
    uint32_t a;
    asm("{ .reg .u64 t; cvta.to.shared.u64 t, %1; cvt.u32.u64 %0, t; }"
        : "=r"(a) : "l"(p));
    return a;
}

__device__ __forceinline__ float warp_sum(float v) {
    #pragma unroll
    for (int off = 16; off > 0; off >>= 1)
        v += __shfl_xor_sync(0xFFFFFFFFu, v, off);
    return v;
}

// Three interleaved butterfly reductions (chains pipeline through MUFU/ALU).
__device__ __forceinline__ void warp_sum3(float& x, float& y, float& z) {
    #pragma unroll
    for (int off = 16; off > 0; off >>= 1) {
        x += __shfl_xor_sync(0xFFFFFFFFu, x, off);
        y += __shfl_xor_sync(0xFFFFFFFFu, y, off);
        z += __shfl_xor_sync(0xFFFFFFFFu, z, off);
    }
}

// One warp per row: fp32 normalize, exact fp32 pos (single reduction phase:
// raw dot reduced alongside the two norms), fp16 copies; zeroes counters.
__global__ void norm_kernel(const float* __restrict__ z1,
                            const float* __restrict__ z2, int N) {
    int warp = (blockIdx.x * blockDim.x + threadIdx.x) >> 5;
    int lane = threadIdx.x & 31;
    if (blockIdx.x == 0 && threadIdx.x == 0) { g_ctr = 0; g_done = 0; }
    if (warp >= N) return;

    const float4 a = ((const float4*)(z1 + (size_t)warp * D))[lane];
    const float4 b = ((const float4*)(z2 + (size_t)warp * D))[lane];

    float sa = a.x * a.x + a.y * a.y + a.z * a.z + a.w * a.w;
    float sb = b.x * b.x + b.y * b.y + b.z * b.z + b.w * b.w;
    float dr = a.x * b.x + a.y * b.y + a.z * b.z + a.w * b.w;
    warp_sum3(sa, sb, dr);

    float inva = 1.0f / fmaxf(sqrtf(sa), 1e-12f);
    float invb = 1.0f / fmaxf(sqrtf(sb), 1e-12f);

    float4 an = make_float4(a.x * inva, a.y * inva, a.z * inva, a.w * inva);
    float4 bn = make_float4(b.x * invb, b.y * invb, b.z * invb, b.w * invb);

    // bake exponent scale 2/ln2 into A so epilogue is a bare ex2.approx
    const float S = 2.8853900817779268f;
    __half2 a01 = __floats2half2_rn(an.x * S, an.y * S);
    __half2 a23 = __floats2half2_rn(an.z * S, an.w * S);
    __half2 b01 = __floats2half2_rn(bn.x, bn.y);
    __half2 b23 = __floats2half2_rn(bn.z, bn.w);

    uint2 pa, pb;
    pa.x = *(uint32_t*)&a01; pa.y = *(uint32_t*)&a23;
    pb.x = *(uint32_t*)&b01; pb.y = *(uint32_t*)&b23;
    ((uint2*)(g_z1h + (size_t)warp * D))[lane] = pa;
    ((uint2*)(g_z2h + (size_t)warp * D))[lane] = pb;

    if (lane == 0) {
        g_pos[warp] = 2.0f * dr * inva * invb;
        g_denom[warp] = 0.0f;
    }
}

__device__ __forceinline__ void ldsm_x4(uint32_t (&r)[4], uint32_t addr) {
    asm volatile("ldmatrix.sync.aligned.m8n8.x4.shared.b16 {%0,%1,%2,%3}, [%4];"
                 : "=r"(r[0]), "=r"(r[1]), "=r"(r[2]), "=r"(r[3]) : "r"(addr));
}

// fp16 in, fp16 accum: C/D fragments are 2 regs of f16x2
__device__ __forceinline__ void hmma_f16acc(uint32_t (&c)[2], const uint32_t (&a)[4],
                                            uint32_t b0, uint32_t b1) {
    asm volatile(
        "mma.sync.aligned.m16n8k16.row.col.f16.f16.f16.f16 "
        "{%0,%1}, {%2,%3,%4,%5}, {%6,%7}, {%0,%1};"
        : "+r"(c[0]), "+r"(c[1])
        : "r"(a[0]), "r"(a[1]), "r"(a[2]), "r"(a[3]), "r"(b0), "r"(b1));
}

__device__ __forceinline__ void cp16(uint32_t dst, const void* src) {
    asm volatile("cp.async.cg.shared.global [%0], [%1], 16;"
                 :: "r"(dst), "l"(src) : "memory");
}

// One tile's k-loop accumulating into `acc`, with the epilogue of the
// PREVIOUS tile (`cprev`) interleaved one fragment-group per kk step.
// All register-array indices are compile-time (no spills).
__device__ __forceinline__ void tile_step(
    uint32_t (&acc)[2][4][2], uint32_t (&cprev)[2][4][2],
    uint32_t a_base, uint32_t b_base, float (&rs)[4]) {
    #pragma unroll
    for (int kk = 0; kk < 8; ++kk) {
        const uint32_t koff = (uint32_t)kk * 32;
        uint32_t a[2][4];
        #pragma unroll
        for (int mf = 0; mf < 2; ++mf)
            ldsm_x4(a[mf], a_base + (uint32_t)(mf * 16) * SROW + koff);
        uint32_t bm[2][4];
        #pragma unroll
        for (int nf2 = 0; nf2 < 2; ++nf2)
            ldsm_x4(bm[nf2], b_base + (uint32_t)(nf2 * 16) * SROW + koff);

        #pragma unroll
        for (int mf = 0; mf < 2; ++mf)
            #pragma unroll
            for (int nf = 0; nf < 4; ++nf)
                hmma_f16acc(acc[mf][nf], a[mf],
                            bm[nf >> 1][nf & 1], bm[nf >> 1][(nf & 1) + 2]);

        {   // deferred epilogue chunk: fragment group = kk of previous tile
            const int mf = kk >> 2, nf = kk & 3;
            float2 f0 = __half22float2(*(__half2*)&cprev[mf][nf][0]);
            float2 f1 = __half22float2(*(__half2*)&cprev[mf][nf][1]);
            float e0, e1, e2, e3;
            asm("ex2.approx.f32 %0, %1;" : "=f"(e0) : "f"(f0.x));
            asm("ex2.approx.f32 %0, %1;" : "=f"(e1) : "f"(f0.y));
            asm("ex2.approx.f32 %0, %1;" : "=f"(e2) : "f"(f1.x));
            asm("ex2.approx.f32 %0, %1;" : "=f"(e3) : "f"(f1.y));
            rs[mf * 2 + 0] += e0 + e1;
            rs[mf * 2 + 1] += e2 + e3;
            cprev[mf][nf][0] = 0u;
            cprev[mf][nf][1] = 0u;
        }
    }
}

// ---------------------------------------------------------------------------
// PERSISTENT FP16-accum HMMA GEMM + fused deferred exp/rowsum + fused loss.
// Grid 148 CTAs (1/SM), 512 threads. Atomic counter pops (row-tile, chunk)
// items; per item the verified R9 16-tile loop runs unchanged. The LAST CTA
// to finish computes the loss over g_denom/g_pos and writes out[0].
// Bogus first-epilogue per item adds 128/row; 8 items/row -> 1024, subtracted.
// ---------------------------------------------------------------------------
__global__ void __launch_bounds__(THREADS, 1)
gemm_hmma16_kernel(float* __restrict__ out, int N) {
    extern __shared__ char smem[];
    const uint32_t sb = smem_u32(smem);
    const int tid = threadIdx.x;
    const int wid = tid >> 5;
    const int lane = tid & 31;
    const int warp_m = wid >> 2;      // 0..3
    const int warp_n = wid & 3;       // 0..3
    const int T = (N / BNT) / JCHUNKS;   // 16 tiles per item (even)
    float* red = (float*)(smem + OFF_RED);
    int* item_sm = (int*)(smem + OFF_ITEM);

    const uint32_t a_base = sb + OFF_A +
        (uint32_t)(warp_m * 32 + (lane & 15)) * SROW + (uint32_t)((lane >> 4) * 16);
    const uint32_t b_lane_off =
        (uint32_t)(warp_n * 32 + (lane & 15)) * SROW + (uint32_t)((lane >> 4) * 16);
    const uint32_t b_base0 = sb + OFF_B0 + b_lane_off;
    const uint32_t b_base1 = sb + OFF_B1 + b_lane_off;

    uint32_t c0[2][4][2], c1[2][4][2];
    #pragma unroll
    for (int mf = 0; mf < 2; ++mf)
        #pragma unroll
        for (int nf = 0; nf < 4; ++nf) {
            c0[mf][nf][0] = 0u; c0[mf][nf][1] = 0u;
            c1[mf][nf][0] = 0u; c1[mf][nf][1] = 0u;
        }

    for (;;) {
        // ---- pop next work item ----
        if (tid == 0) item_sm[0] = atomicAdd(&g_ctr, 1);
        __syncthreads();                 // item visible; prev item fully done
        const int item = item_sm[0];
        if (item >= NITEMS) break;
        const int i0 = (item >> 3) * BM;       // row tile
        const int jt0 = (item & 7) * T;        // chunk start tile

        // Load A tile (128x128 fp16) into padded smem.
        {
            const uint4* A4 = (const uint4*)(g_z1h + (size_t)i0 * D);
            #pragma unroll
            for (int t = 0; t < 4; ++t) {
                int idx = tid + t * THREADS;        // 0..2047
                int r = idx >> 4, c = idx & 15;
                *(uint4*)(smem + OFF_A + r * SROW + c * 16) = A4[idx];
            }
        }
        // Prologue: B tile jt0 -> buf0
        {
            const char* B = (const char*)(g_z2h + (size_t)jt0 * BNT * D);
            #pragma unroll
            for (int t = 0; t < 4; ++t) {
                int idx = tid + t * THREADS;
                int r = idx >> 4, c = idx & 15;
                cp16(sb + OFF_B0 + r * SROW + c * 16, B + (size_t)r * 256 + c * 16);
            }
            asm volatile("cp.async.commit_group;" ::: "memory");
        }
        if (tid < 128) red[tid] = 0.f;

        float rs[4] = {0.f, 0.f, 0.f, 0.f};

        for (int t = 0; t < T; t += 2) {
            // sub-iter A: tile t (buf0, acc c0, epilogue c1 = tile t-1)
            __syncthreads();   // everyone done reading buf1 (or: A/buf0 ready)
            {   // t+1 < T always (T even)
                const char* B = (const char*)(g_z2h + (size_t)(jt0 + t + 1) * BNT * D);
                #pragma unroll
                for (int u = 0; u < 4; ++u) {
                    int idx = tid + u * THREADS;
                    int r = idx >> 4, ch = idx & 15;
                    cp16(sb + OFF_B1 + r * SROW + ch * 16, B + (size_t)r * 256 + ch * 16);
                }
                asm volatile("cp.async.commit_group;" ::: "memory");
                asm volatile("cp.async.wait_group 1;" ::: "memory");
            }
            __syncthreads();   // buf0 visible
            tile_step(c0, c1, a_base, b_base0, rs);

            // sub-iter B: tile t+1 (buf1, acc c1, epilogue c0 = tile t)
            __syncthreads();   // everyone done reading buf0
            if (t + 2 < T) {
                const char* B = (const char*)(g_z2h + (size_t)(jt0 + t + 2) * BNT * D);
                #pragma unroll
                for (int u = 0; u < 4; ++u) {
                    int idx = tid + u * THREADS;
                    int r = idx >> 4, ch = idx & 15;
                    cp16(sb + OFF_B0 + r * SROW + ch * 16, B + (size_t)r * 256 + ch * 16);
                }
                asm volatile("cp.async.commit_group;" ::: "memory");
                asm volatile("cp.async.wait_group 1;" ::: "memory");
            } else {
                asm volatile("cp.async.wait_group 0;" ::: "memory");
            }
            __syncthreads();   // buf1 visible
            tile_step(c1, c0, a_base, b_base1, rs);
        }

        // final epilogue: c1 holds tile T-1 (zero it for reuse next item)
        #pragma unroll
        for (int mf = 0; mf < 2; ++mf) {
            float lo = 0.f, hi = 0.f;
            #pragma unroll
            for (int nf = 0; nf < 4; ++nf) {
                float2 f0 = __half22float2(*(__half2*)&c1[mf][nf][0]);
                float2 f1 = __half22float2(*(__half2*)&c1[mf][nf][1]);
                float e0, e1, e2, e3;
                asm("ex2.approx.f32 %0, %1;" : "=f"(e0) : "f"(f0.x));
                asm("ex2.approx.f32 %0, %1;" : "=f"(e1) : "f"(f0.y));
                asm("ex2.approx.f32 %0, %1;" : "=f"(e2) : "f"(f1.x));
                asm("ex2.approx.f32 %0, %1;" : "=f"(e3) : "f"(f1.y));
                lo += e0 + e1;
                hi += e2 + e3;
                c1[mf][nf][0] = 0u;
                c1[mf][nf][1] = 0u;
            }
            rs[mf * 2 + 0] += lo;
            rs[mf * 2 + 1] += hi;
        }

        // reduce rs across the 4 lanes of each quad
        #pragma unroll
        for (int i = 0; i < 4; ++i) {
            rs[i] += __shfl_xor_sync(0xFFFFFFFFu, rs[i], 1);
            rs[i] += __shfl_xor_sync(0xFFFFFFFFu, rs[i], 2);
        }
        __syncthreads();   // red zeroed (above) and all compute done
        if ((lane & 3) == 0) {
            #pragma unroll
            for (int mf = 0; mf < 2; ++mf)
                #pragma unroll
                for (int sub = 0; sub < 2; ++sub) {
                    int row = warp_m * 32 + mf * 16 + sub * 8 + (lane >> 2);
                    atomicAdd(&red[row], rs[mf * 2 + sub]);
                }
        }
        __syncthreads();
        if (tid < 128) atomicAdd(&g_denom[i0 + tid], red[tid]);
        // loop back: first __syncthreads of next item protects A/red reuse
    }

    // ---- fused loss: last CTA to arrive reduces g_denom/g_pos -> out[0] ----
    __threadfence();   // make this CTA's g_denom atomics globally visible
    if (tid == 0) item_sm[0] = atomicAdd(&g_done, 1);
    __syncthreads();
    if (item_sm[0] == GRID_P - 1) {
        const float BOGUS = 128.0f * (float)JCHUNKS;
        const float LN2 = 0.6931471805599453f;
        float s = 0.f;
        for (int i = tid; i < N; i += THREADS) {
            float dv = __ldcg(&g_denom[i]) - BOGUS + 1e-8f;
            float lg;
            asm("lg2.approx.f32 %0, %1;" : "=f"(lg) : "f"(dv));
            s += lg * LN2 - __ldcg(&g_pos[i]);
        }
        s = warp_sum(s);
        float* wred = (float*)(smem + OFF_B0);   // free scratch
        if (lane == 0) wred[wid] = s;
        __syncthreads();
        if (tid == 0) {
            float tot = 0.f;
            #pragma unroll
            for (int w = 0; w < 16; ++w) tot += wred[w];
            out[0] = tot / (float)N;
        }
    }
}

extern "C" void kernel_launch(void* const* d_in, const int* in_sizes, int n_in,
                              void* d_out, int out_size) {
    const float* z1 = (const float*)d_in[0];
    const float* z2 = (const float*)d_in[1];
    float* out = (float*)d_out;
    const int N = in_sizes[0] / D;  // 16384

    cudaFuncSetAttribute(gemm_hmma16_kernel,
                         cudaFuncAttributeMaxDynamicSharedMemorySize,
                         (int)SMEM_BYTES);

    norm_kernel<<<(N + 7) / 8, 256>>>(z1, z2, N);
    gemm_hmma16_kernel<<<GRID_P, THREADS, SMEM_BYTES>>>(out, N);
}

// round 17
// speedup vs baseline: 1.7007x; 1.0126x over previous
#include <cuda_runtime.h>
#include <cuda_fp16.h>
#include <math.h>
#include <stdint.h>

#define D 128
#define N_MAX 16384
#define BM 128
#define BNT 128
#define THREADS 512
#define GRID_P 152           // GB300 has 152 SMs; harmless if fewer usable

// Work decomposition: per row-tile (128 of them):
//   7 big items of 16 tiles (tiles 0..111) + 4 small items of 4 tiles (112..127)
#define BIG_ITEMS (128 * 7)      // 896
#define NITEMS (128 * 11)        // 1408
#define ITEMS_PER_ROW 11         // bogus epilogues per row

// Scratch (allocation-free rule: __device__ globals)
__device__ __half g_z1h[N_MAX * D];   // fp16, pre-scaled by 2/ln2
__device__ __half g_z2h[N_MAX * D];   // fp16
__device__ float g_denom[N_MAX];
__device__ float g_pos[N_MAX];
__device__ int g_ctr;                 // persistent work counter

// padded smem row stride: 128 fp16 + 8 pad = 136 elems = 272 bytes
#define SROW 272
#define TILE_BYTES (128 * SROW)          // 34816
#define OFF_A 0
#define OFF_B0 TILE_BYTES
#define OFF_B1 (2 * TILE_BYTES)
#define OFF_RED (3 * TILE_BYTES)
#define OFF_ITEM (OFF_RED + 128 * 4)
#define SMEM_BYTES (OFF_ITEM + 16)

__device__ __forceinline__ uint32_t smem_u32(const void* p) {
    uint32_t a;
    asm("{ .reg .u64 t; cvta.to.shared.u64 t, %1; cvt.u32.u64 %0, t; }"
        : "=r"(a) : "l"(p));
    return a;
}

__device__ __forceinline__ float warp_sum(float v) {
    #pragma unroll
    for (int off = 16; off > 0; off >>= 1)
        v += __shfl_xor_sync(0xFFFFFFFFu, v, off);
    return v;
}

// One warp per row: fp32 normalize, exact fp32 pos, fp16 copies;
// zeroes g_denom, g_ctr, out[0].  (R14-verified body.)
__global__ void norm_kernel(const float* __restrict__ z1,
                            const float* __restrict__ z2,
                            float* __restrict__ out, int N) {
    int warp = (blockIdx.x * blockDim.x + threadIdx.x) >> 5;
    int lane = threadIdx.x & 31;
    if (blockIdx.x == 0 && threadIdx.x == 0) { out[0] = 0.0f; g_ctr = 0; }
    if (warp >= N) return;

    const float4 a = ((const float4*)(z1 + (size_t)warp * D))[lane];
    const float4 b = ((const float4*)(z2 + (size_t)warp * D))[lane];

    float sa = a.x * a.x + a.y * a.y + a.z * a.z + a.w * a.w;
    float sb = b.x * b.x + b.y * b.y + b.z * b.z + b.w * b.w;
    sa = warp_sum(sa);
    sb = warp_sum(sb);

    float inva = 1.0f / fmaxf(sqrtf(sa), 1e-12f);
    float invb = 1.0f / fmaxf(sqrtf(sb), 1e-12f);

    float4 an = make_float4(a.x * inva, a.y * inva, a.z * inva, a.w * inva);
    float4 bn = make_float4(b.x * invb, b.y * invb, b.z * invb, b.w * invb);

    // bake exponent scale 2/ln2 into A so epilogue is a bare ex2.approx
    const float S = 2.8853900817779268f;
    __half2 a01 = __floats2half2_rn(an.x * S, an.y * S);
    __half2 a23 = __floats2half2_rn(an.z * S, an.w * S);
    __half2 b01 = __floats2half2_rn(bn.x, bn.y);
    __half2 b23 = __floats2half2_rn(bn.z, bn.w);

    uint2 pa, pb;
    pa.x = *(uint32_t*)&a01; pa.y = *(uint32_t*)&a23;
    pb.x = *(uint32_t*)&b01; pb.y = *(uint32_t*)&b23;
    ((uint2*)(g_z1h + (size_t)warp * D))[lane] = pa;
    ((uint2*)(g_z2h + (size_t)warp * D))[lane] = pb;

    float d = an.x * bn.x + an.y * bn.y + an.z * bn.z + an.w * bn.w;
    d = warp_sum(d);
    if (lane == 0) {
        g_pos[warp] = 2.0f * d;
        g_denom[warp] = 0.0f;
    }
}

__device__ __forceinline__ void ldsm_x4(uint32_t (&r)[4], uint32_t addr) {
    asm volatile("ldmatrix.sync.aligned.m8n8.x4.shared.b16 {%0,%1,%2,%3}, [%4];"
                 : "=r"(r[0]), "=r"(r[1]), "=r"(r[2]), "=r"(r[3]) : "r"(addr));
}

// fp16 in, fp16 accum: C/D fragments are 2 regs of f16x2
__device__ __forceinline__ void hmma_f16acc(uint32_t (&c)[2], const uint32_t (&a)[4],
                                            uint32_t b0, uint32_t b1) {
    asm volatile(
        "mma.sync.aligned.m16n8k16.row.col.f16.f16.f16.f16 "
        "{%0,%1}, {%2,%3,%4,%5}, {%6,%7}, {%0,%1};"
        : "+r"(c[0]), "+r"(c[1])
        : "r"(a[0]), "r"(a[1]), "r"(a[2]), "r"(a[3]), "r"(b0), "r"(b1));
}

__device__ __forceinline__ void cp16(uint32_t dst, const void* src) {
    asm volatile("cp.async.cg.shared.global [%0], [%1], 16;"
                 :: "r"(dst), "l"(src) : "memory");
}

// One tile's k-loop accumulating into `acc`, with the epilogue of the
// PREVIOUS tile (`cprev`) interleaved one fragment-group per kk step.
// All register-array indices are compile-time (no spills).
__device__ __forceinline__ void tile_step(
    uint32_t (&acc)[2][4][2], uint32_t (&cprev)[2][4][2],
    uint32_t a_base, uint32_t b_base, float (&rs)[4]) {
    #pragma unroll
    for (int kk = 0; kk < 8; ++kk) {
        const uint32_t koff = (uint32_t)kk * 32;
        uint32_t a[2][4];
        #pragma unroll
        for (int mf = 0; mf < 2; ++mf)
            ldsm_x4(a[mf], a_base + (uint32_t)(mf * 16) * SROW + koff);
        uint32_t bm[2][4];
        #pragma unroll
        for (int nf2 = 0; nf2 < 2; ++nf2)
            ldsm_x4(bm[nf2], b_base + (uint32_t)(nf2 * 16) * SROW + koff);

        #pragma unroll
        for (int mf = 0; mf < 2; ++mf)
            #pragma unroll
            for (int nf = 0; nf < 4; ++nf)
                hmma_f16acc(acc[mf][nf], a[mf],
                            bm[nf >> 1][nf & 1], bm[nf >> 1][(nf & 1) + 2]);

        {   // deferred epilogue chunk: fragment group = kk of previous tile
            const int mf = kk >> 2, nf = kk & 3;
            float2 f0 = __half22float2(*(__half2*)&cprev[mf][nf][0]);
            float2 f1 = __half22float2(*(__half2*)&cprev[mf][nf][1]);
            float e0, e1, e2, e3;
            asm("ex2.approx.f32 %0, %1;" : "=f"(e0) : "f"(f0.x));
            asm("ex2.approx.f32 %0, %1;" : "=f"(e1) : "f"(f0.y));
            asm("ex2.approx.f32 %0, %1;" : "=f"(e2) : "f"(f1.x));
            asm("ex2.approx.f32 %0, %1;" : "=f"(e3) : "f"(f1.y));
            rs[mf * 2 + 0] += e0 + e1;
            rs[mf * 2 + 1] += e2 + e3;
            cprev[mf][nf][0] = 0u;
            cprev[mf][nf][1] = 0u;
        }
    }
}

// ---------------------------------------------------------------------------
// PERSISTENT FP16-accum HMMA GEMM + fused deferred exp/rowsum.
// Grid 152 CTAs, 512 threads. Atomic counter pops graded items:
//   item < 896:  big  = (row-tile, 16 tiles) popped first
//   item >= 896: small = (row-tile, 4 tiles)  pack the tail
// Bogus first-epilogue per item adds 128/row; 11 items/row -> 1408, subtracted.
// ---------------------------------------------------------------------------
__global__ void __launch_bounds__(THREADS, 1)
gemm_hmma16_kernel(int N) {
    extern __shared__ char smem[];
    const uint32_t sb = smem_u32(smem);
    const int tid = threadIdx.x;
    const int wid = tid >> 5;
    const int lane = tid & 31;
    const int warp_m = wid >> 2;      // 0..3
    const int warp_n = wid & 3;       // 0..3
    float* red = (float*)(smem + OFF_RED);
    int* item_sm = (int*)(smem + OFF_ITEM);

    const uint32_t a_base = sb + OFF_A +
        (uint32_t)(warp_m * 32 + (lane & 15)) * SROW + (uint32_t)((lane >> 4) * 16);
    const uint32_t b_lane_off =
        (uint32_t)(warp_n * 32 + (lane & 15)) * SROW + (uint32_t)((lane >> 4) * 16);
    const uint32_t b_base0 = sb + OFF_B0 + b_lane_off;
    const uint32_t b_base1 = sb + OFF_B1 + b_lane_off;

    uint32_t c0[2][4][2], c1[2][4][2];
    #pragma unroll
    for (int mf = 0; mf < 2; ++mf)
        #pragma unroll
        for (int nf = 0; nf < 4; ++nf) {
            c0[mf][nf][0] = 0u; c0[mf][nf][1] = 0u;
            c1[mf][nf][0] = 0u; c1[mf][nf][1] = 0u;
        }

    for (;;) {
        // ---- pop next work item ----
        if (tid == 0) item_sm[0] = atomicAdd(&g_ctr, 1);
        __syncthreads();                 // item visible; prev item fully done
        const int item = item_sm[0];
        if (item >= NITEMS) break;
        int i0, jt0, T;
        if (item < BIG_ITEMS) {          // big: 16 tiles
            i0 = (item / 7) * BM;
            jt0 = (item % 7) * 16;
            T = 16;
        } else {                         // small: 4 tiles (tail packing)
            int e = item - BIG_ITEMS;
            i0 = (e >> 2) * BM;
            jt0 = 112 + (e & 3) * 4;
            T = 4;
        }

        // Load A tile (128x128 fp16) into padded smem.
        {
            const uint4* A4 = (const uint4*)(g_z1h + (size_t)i0 * D);
            #pragma unroll
            for (int t = 0; t < 4; ++t) {
                int idx = tid + t * THREADS;        // 0..2047
                int r = idx >> 4, c = idx & 15;
                *(uint4*)(smem + OFF_A + r * SROW + c * 16) = A4[idx];
            }
        }
        // Prologue: B tile jt0 -> buf0
        {
            const char* B = (const char*)(g_z2h + (size_t)jt0 * BNT * D);
            #pragma unroll
            for (int t = 0; t < 4; ++t) {
                int idx = tid + t * THREADS;
                int r = idx >> 4, c = idx & 15;
                cp16(sb + OFF_B0 + r * SROW + c * 16, B + (size_t)r * 256 + c * 16);
            }
            asm volatile("cp.async.commit_group;" ::: "memory");
        }
        if (tid < 128) red[tid] = 0.f;

        float rs[4] = {0.f, 0.f, 0.f, 0.f};

        for (int t = 0; t < T; t += 2) {
            // sub-iter A: tile t (buf0, acc c0, epilogue c1 = tile t-1)
            __syncthreads();   // everyone done reading buf1 (or: A/buf0 ready)
            {   // t+1 < T always (T even)
                const char* B = (const char*)(g_z2h + (size_t)(jt0 + t + 1) * BNT * D);
                #pragma unroll
                for (int u = 0; u < 4; ++u) {
                    int idx = tid + u * THREADS;
                    int r = idx >> 4, ch = idx & 15;
                    cp16(sb + OFF_B1 + r * SROW + ch * 16, B + (size_t)r * 256 + ch * 16);
                }
                asm volatile("cp.async.commit_group;" ::: "memory");
                asm volatile("cp.async.wait_group 1;" ::: "memory");
            }
            __syncthreads();   // buf0 visible
            tile_step(c0, c1, a_base, b_base0, rs);

            // sub-iter B: tile t+1 (buf1, acc c1, epilogue c0 = tile t)
            __syncthreads();   // everyone done reading buf0
            if (t + 2 < T) {
                const char* B = (const char*)(g_z2h + (size_t)(jt0 + t + 2) * BNT * D);
                #pragma unroll
                for (int u = 0; u < 4; ++u) {
                    int idx = tid + u * THREADS;
                    int r = idx >> 4, ch = idx & 15;
                    cp16(sb + OFF_B0 + r * SROW + ch * 16, B + (size_t)r * 256 + ch * 16);
                }
                asm volatile("cp.async.commit_group;" ::: "memory");
                asm volatile("cp.async.wait_group 1;" ::: "memory");
            } else {
                asm volatile("cp.async.wait_group 0;" ::: "memory");
            }
            __syncthreads();   // buf1 visible
            tile_step(c1, c0, a_base, b_base1, rs);
        }

        // final epilogue: c1 holds tile T-1 (zero it for reuse next item)
        #pragma unroll
        for (int mf = 0; mf < 2; ++mf) {
            float lo = 0.f, hi = 0.f;
            #pragma unroll
            for (int nf = 0; nf < 4; ++nf) {
                float2 f0 = __half22float2(*(__half2*)&c1[mf][nf][0]);
                float2 f1 = __half22float2(*(__half2*)&c1[mf][nf][1]);
                float e0, e1, e2, e3;
                asm("ex2.approx.f32 %0, %1;" : "=f"(e0) : "f"(f0.x));
                asm("ex2.approx.f32 %0, %1;" : "=f"(e1) : "f"(f0.y));
                asm("ex2.approx.f32 %0, %1;" : "=f"(e2) : "f"(f1.x));
                asm("ex2.approx.f32 %0, %1;" : "=f"(e3) : "f"(f1.y));
                lo += e0 + e1;
                hi += e2 + e3;
                c1[mf][nf][0] = 0u;
                c1[mf][nf][1] = 0u;
            }
            rs[mf * 2 + 0] += lo;
            rs[mf * 2 + 1] += hi;
        }

        // reduce rs across the 4 lanes of each quad
        #pragma unroll
        for (int i = 0; i < 4; ++i) {
            rs[i] += __shfl_xor_sync(0xFFFFFFFFu, rs[i], 1);
            rs[i] += __shfl_xor_sync(0xFFFFFFFFu, rs[i], 2);
        }
        __syncthreads();   // red zeroed (above) and all compute done
        if ((lane & 3) == 0) {
            #pragma unroll
            for (int mf = 0; mf < 2; ++mf)
                #pragma unroll
                for (int sub = 0; sub < 2; ++sub) {
                    int row = warp_m * 32 + mf * 16 + sub * 8 + (lane >> 2);
                    atomicAdd(&red[row], rs[mf * 2 + sub]);
                }
        }
        __syncthreads();
        if (tid < 128) atomicAdd(&g_denom[i0 + tid], red[tid]);
        // loop back: first __syncthreads of next item protects A/red reuse
    }
}

// 64 blocks x 256 threads; per-block partial, atomicAdd into out[0].
// log(x) = lg2.approx(x) * ln2 (MUFU instead of slow logf).
__global__ void loss_kernel(float* __restrict__ out, int N) {
    __shared__ float smr[256];
    const float BOGUS = 128.0f * (float)ITEMS_PER_ROW;   // 1408 per row
    const float LN2 = 0.6931471805599453f;
    int i = blockIdx.x * 256 + threadIdx.x;        // N = 64*256 exactly
    float dv = g_denom[i] - BOGUS + 1e-8f;
    float lg;
    asm("lg2.approx.f32 %0, %1;" : "=f"(lg) : "f"(dv));
    float s = lg * LN2 - g_pos[i];
    smr[threadIdx.x] = s;
    __syncthreads();
    #pragma unroll
    for (int off = 128; off > 0; off >>= 1) {
        if (threadIdx.x < off) smr[threadIdx.x] += smr[threadIdx.x + off];
        __syncthreads();
    }
    if (threadIdx.x == 0) atomicAdd(out, smr[0] / (float)N);
}

extern "C" void kernel_launch(void* const* d_in, const int* in_sizes, int n_in,
                              void* d_out, int out_size) {
    const float* z1 = (const float*)d_in[0];
    const float* z2 = (const float*)d_in[1];
    float* out = (float*)d_out;
    const int N = in_sizes[0] / D;  // 16384

    cudaFuncSetAttribute(gemm_hmma16_kernel,
                         cudaFuncAttributeMaxDynamicSharedMemorySize,
                         (int)SMEM_BYTES);

    norm_kernel<<<(N + 7) / 8, 256>>>(z1, z2, out, N);
    gemm_hmma16_kernel<<<GRID_P, THREADS, SMEM_BYTES>>>(N);
    loss_kernel<<<N / 256, 256>>>(out, N);
}